// round 15
// baseline (speedup 1.0000x reference)
#include <cuda_runtime.h>
#include <math.h>
#include <stdint.h>

// Problem constants
#define Bn 4
#define Tn 2048
#define Dn 1024
#define Hn 16
#define Sn 64
#define NC 32
#define BT (Bn*Tn)   // 8192 rows

typedef unsigned long long u64;

// ---------------- scratch ----------------
__device__ int4  g_xq8[4][BT*Dn/16];
__device__ float g_xscale[4][BT];
__device__ int4  g_wq8[5][Dn*Dn/16];
__device__ float g_wscale[5];
__device__ int4  g_zq8[BT*Dn/16];
__device__ float g_zscale[BT];
__device__ float g_rkvg[4][BT*Dn];
__device__ float g_y[BT*Dn];
__device__ float g_local[Bn*Hn*NC*Sn*Sn];
__device__ float g_init [Bn*Hn*NC*Sn*Sn];
__device__ float g_wpow[65*1024];
__device__ float g_ue[Hn*Sn];

// ---------------- f32x2 packed helpers ----------------
#define F2MUL(d, a, b)    asm("mul.rn.f32x2 %0, %1, %2;" : "=l"(d) : "l"(a), "l"(b))
#define F2FMA(d, a, b, c) asm("fma.rn.f32x2 %0, %1, %2, %3;" : "=l"(d) : "l"(a), "l"(b), "l"(c))
__device__ __forceinline__ u64 pk(float x, float y) {
    u64 r; asm("mov.b64 %0, {%1, %2};" : "=l"(r) : "f"(x), "f"(y)); return r;
}

// ---------------- reductions ----------------
__device__ __forceinline__ double wrD(double v) {
    #pragma unroll
    for (int o = 16; o; o >>= 1) v += __shfl_xor_sync(0xffffffffu, v, o);
    return v;
}

// 64-thread (2-warp) block reduce; caller provides a distinct 2-slot smem region per call
__device__ __forceinline__ double red64(double v, double* sh2, int lane, int w) {
    v = wrD(v);
    if (lane == 0) sh2[w] = v;
    __syncthreads();
    return sh2[0] + sh2[1];
}

// ILP fp64 tree over 16 floats
#define TREE16(res, expr_i) do { \
    double a0 = 0.0, a1 = 0.0, a2 = 0.0, a3 = 0.0; \
    _Pragma("unroll") \
    for (int _j = 0; _j < 4; _j++) { \
        { int i = 4*_j + 0; a0 += (double)(expr_i); } \
        { int i = 4*_j + 1; a1 += (double)(expr_i); } \
        { int i = 4*_j + 2; a2 += (double)(expr_i); } \
        { int i = 4*_j + 3; a3 += (double)(expr_i); } \
    } \
    res = (a0 + a1) + (a2 + a3); \
} while (0)

// block reduce for k_wscale only (256 threads)
__device__ __forceinline__ double brD(double v, double* red) {
    int tid = threadIdx.x, lane = tid & 31, wid = tid >> 5;
    int nw = blockDim.x >> 5;
    v = wrD(v);
    if (lane == 0) red[wid] = v;
    __syncthreads();
    if (tid == 0) {
        double r = red[0];
        for (int i = 1; i < nw; i++) r += red[i];
        red[0] = r;
    }
    __syncthreads();
    double r = red[0];
    __syncthreads();
    return r;
}

// ---------------- misc GEMM helpers ----------------
__device__ __forceinline__ uint32_t smem_u32(const void* p) {
    uint32_t a;
    asm("{ .reg .u64 t; cvta.to.shared.u64 t, %1; cvt.u32.u64 %0, t; }" : "=r"(a) : "l"(p));
    return a;
}
__device__ __forceinline__ void cp16(uint32_t dst, const void* src) {
    asm volatile("cp.async.cg.shared.global [%0], [%1], 16;" :: "r"(dst), "l"(src) : "memory");
}
#define CPCOMMIT()  asm volatile("cp.async.commit_group;" ::: "memory")
#define CPWAIT1()   asm volatile("cp.async.wait_group 1;" ::: "memory")
#define CPWAIT0()   asm volatile("cp.async.wait_group 0;" ::: "memory")
#define LDSM4(r, addr) \
    asm volatile("ldmatrix.sync.aligned.m8n8.x4.shared.b16 {%0,%1,%2,%3}, [%4];" \
        : "=r"((r)[0]), "=r"((r)[1]), "=r"((r)[2]), "=r"((r)[3]) : "r"(addr))
#define MMA8(c, a, b0, b1) \
    asm volatile("mma.sync.aligned.m16n8k32.row.col.s32.s8.s8.s32 " \
        "{%0,%1,%2,%3}, {%4,%5,%6,%7}, {%8,%9}, {%0,%1,%2,%3};" \
        : "+r"((c)[0]), "+r"((c)[1]), "+r"((c)[2]), "+r"((c)[3]) \
        : "r"((a)[0]), "r"((a)[1]), "r"((a)[2]), "r"((a)[3]), "r"(b0), "r"(b1))

// ---------------- precompute ----------------
__global__ void k_params(const float* __restrict__ log_decay, const float* __restrict__ u) {
    int i = threadIdx.x;
    float eld = expf(log_decay[i]);
    float wf  = expf(-eld);
    float lw  = logf(fmaxf(wf, 1e-38f));
    for (int n = 0; n <= 64; n++)
        g_wpow[n * 1024 + i] = expf(__fmul_rn((float)n, lw));
    g_ue[i] = expf(u[i]);
}

// ---------------- weight quantization ----------------
__global__ void k_wscale(const float* __restrict__ w) {
    __shared__ double red[8];
    const float* p = w + (size_t)blockIdx.x * Dn * Dn;
    double s = 0.0;
    for (int i = threadIdx.x; i < Dn * Dn; i += 256) s += (double)fabsf(p[i]);
    double tot = brD(s, red);
    if (threadIdx.x == 0)
        g_wscale[blockIdx.x] = fmaxf((float)(tot / (double)(Dn * Dn)), 1e-8f);
}

__global__ void k_wquant(const float* __restrict__ w) {
    int i = blockIdx.x * 256 + threadIdx.x;
    int m = i / (Dn * Dn);
    float s  = g_wscale[m];
    float vn = __fdiv_rn(w[i], s);
    vn = fminf(fmaxf(vn, -1.f), 1.f);
    ((signed char*)g_wq8)[i] = (signed char)(int)rintf(vn);
}

// ---------------- int8 pack+store: 16 consecutive bytes per thread ----------------
__device__ __forceinline__ void store_q16(signed char* base, const float* yv, float scale) {
    int w[4];
    #pragma unroll
    for (int j = 0; j < 4; j++) {
        int q0 = (int)rintf(fminf(fmaxf(__fdiv_rn(yv[4*j+0], scale), -127.f), 127.f));
        int q1 = (int)rintf(fminf(fmaxf(__fdiv_rn(yv[4*j+1], scale), -127.f), 127.f));
        int q2 = (int)rintf(fminf(fmaxf(__fdiv_rn(yv[4*j+2], scale), -127.f), 127.f));
        int q3 = (int)rintf(fminf(fmaxf(__fdiv_rn(yv[4*j+3], scale), -127.f), 127.f));
        w[j] = (q0 & 0xff) | ((q1 & 0xff) << 8) | ((q2 & 0xff) << 16) | ((q3 & 0xff) << 24);
    }
    *(int4*)base = make_int4(w[0], w[1], w[2], w[3]);
}

// ---------------- token shift + LN + act quant: 64 threads (2 warps) per row ----------------
__global__ void __launch_bounds__(64)
k_prep(const float* __restrict__ x,
       const float* __restrict__ mu_r, const float* __restrict__ mu_k,
       const float* __restrict__ mu_v, const float* __restrict__ mu_g,
       const float* __restrict__ ln_g, const float* __restrict__ ln_b) {
    int row  = blockIdx.x;
    int tid  = threadIdx.x;            // 0..63, owns d = tid*16 .. +15
    int lane = tid & 31, w = tid >> 5;
    int t    = row % Tn;
    __shared__ double sh[24];          // 2 slots per reduction, 12 reductions

    const float4* xr = (const float4*)(x + (size_t)row * Dn) + tid * 4;
    const float4* xp = (const float4*)(x + (size_t)(row - 1) * Dn) + tid * 4;

    float xv[16], dx[16];
    #pragma unroll
    for (int j = 0; j < 4; j++) {
        float4 a = xr[j];
        float4 p = (t > 0) ? xp[j] : make_float4(0.f, 0.f, 0.f, 0.f);
        xv[4*j+0] = a.x; xv[4*j+1] = a.y; xv[4*j+2] = a.z; xv[4*j+3] = a.w;
        dx[4*j+0] = __fsub_rn(p.x, a.x); dx[4*j+1] = __fsub_rn(p.y, a.y);
        dx[4*j+2] = __fsub_rn(p.z, a.z); dx[4*j+3] = __fsub_rn(p.w, a.w);
    }

    #pragma unroll 1
    for (int v = 0; v < 4; v++) {
        const float* mu = (v == 0) ? mu_r : (v == 1) ? mu_k : (v == 2) ? mu_v : mu_g;
        const float4* muv = (const float4*)mu + tid * 4;
        float inp[16];
        #pragma unroll
        for (int j = 0; j < 4; j++) {
            float4 m = muv[j];
            float mm[4] = {m.x, m.y, m.z, m.w};
            #pragma unroll
            for (int q = 0; q < 4; q++) {
                int i = 4*j + q;
                inp[i] = __fadd_rn(xv[i], __fmul_rn(dx[i], mm[q]));
            }
        }
        double s;
        TREE16(s, inp[i]);
        float mean = (float)(red64(s, sh + v * 6 + 0, lane, w) * (1.0 / Dn));

        #pragma unroll
        for (int i = 0; i < 16; i++) inp[i] = __fsub_rn(inp[i], mean);   // dev
        double s2;
        TREE16(s2, __fmul_rn(inp[i], inp[i]));
        float var  = (float)(red64(s2, sh + v * 6 + 2, lane, w) * (1.0 / Dn));
        float rstd = (float)(1.0 / sqrt((double)__fadd_rn(var, 1e-5f)));

        const float4* gp = (const float4*)(ln_g + v * Dn) + tid * 4;
        const float4* bp = (const float4*)(ln_b + v * Dn) + tid * 4;
        #pragma unroll
        for (int j = 0; j < 4; j++) {
            float4 gg = gp[j], bb = bp[j];
            float ga[4] = {gg.x, gg.y, gg.z, gg.w};
            float ba[4] = {bb.x, bb.y, bb.z, bb.w};
            #pragma unroll
            for (int q = 0; q < 4; q++) {
                int i = 4*j + q;
                float t1 = __fmul_rn(inp[i], rstd);
                inp[i] = __fadd_rn(__fmul_rn(t1, ga[q]), ba[q]);         // yv
            }
        }
        double sa;
        TREE16(sa, fabsf(inp[i]));
        float meanabs = (float)(red64(sa, sh + v * 6 + 4, lane, w) * (1.0 / Dn));
        float clipv = __fmul_rn(fmaxf(meanabs, 1e-8f), 2.5f);
        float scale = __fdiv_rn(clipv, 127.f);
        if (tid == 0) g_xscale[v][row] = scale;
        store_q16((signed char*)g_xq8[v] + (size_t)row * Dn + tid * 16, inp, scale);
    }
}

// ---------------- int8 tensor-core GEMM via mma.sync (exact int32 accum) ----------------
#define ROWB 80
__global__ void __launch_bounds__(256, 2)
k_gemm_i8(const int4* __restrict__ A, const int4* __restrict__ W,
          const float* __restrict__ rowscale, const float* __restrict__ wsp,
          float* __restrict__ Cm) {
    __shared__ __align__(16) signed char As[2][128 * ROWB];
    __shared__ __align__(16) signed char Bs[2][128 * ROWB];
    int tid = threadIdx.x, lid = tid & 31, wid = tid >> 5;
    int m0 = blockIdx.y * 128, n0 = blockIdx.x * 128;
    int wm = (wid & 1) * 64, wn = (wid >> 1) * 32;

    int lrow = tid >> 1;
    int lc   = (tid & 1) * 2;
    const int4* Ag = A + (size_t)(m0 + lrow) * 64 + lc;
    const int4* Wg = W + (size_t)(n0 + lrow) * 64 + lc;
    uint32_t soff = (uint32_t)(lrow * ROWB + lc * 16);
    uint32_t sa[2] = {smem_u32(As[0]), smem_u32(As[1])};
    uint32_t sbm[2] = {smem_u32(Bs[0]), smem_u32(Bs[1])};

    int arow   = (lid & 7) + ((lid >> 3) & 1) * 8;
    int akhalf = lid >> 4;
    int brow   = (lid & 7) + (lid >> 4) * 8;
    int bkhalf = (lid >> 3) & 1;
    uint32_t aaddr[2][4], baddr[2][2];
    #pragma unroll
    for (int buf = 0; buf < 2; buf++) {
        #pragma unroll
        for (int mt = 0; mt < 4; mt++)
            aaddr[buf][mt] = sa[buf] + (uint32_t)((wm + mt * 16 + arow) * ROWB + akhalf * 16);
        #pragma unroll
        for (int bt = 0; bt < 2; bt++)
            baddr[buf][bt] = sbm[buf] + (uint32_t)((wn + bt * 16 + brow) * ROWB + bkhalf * 16);
    }

    int c[4][4][4];
    #pragma unroll
    for (int mt = 0; mt < 4; mt++)
        #pragma unroll
        for (int nt = 0; nt < 4; nt++)
            #pragma unroll
            for (int q = 0; q < 4; q++) c[mt][nt][q] = 0;

    cp16(sa[0] + soff,       Ag);
    cp16(sa[0] + soff + 16,  Ag + 1);
    cp16(sbm[0] + soff,      Wg);
    cp16(sbm[0] + soff + 16, Wg + 1);
    CPCOMMIT();

    for (int kb = 0; kb < 16; kb++) {
        int buf = kb & 1;
        if (kb < 15) {
            const int4* an = Ag + (kb + 1) * 4;
            const int4* wn_ = Wg + (kb + 1) * 4;
            int nb = buf ^ 1;
            cp16(sa[nb] + soff,       an);
            cp16(sa[nb] + soff + 16,  an + 1);
            cp16(sbm[nb] + soff,      wn_);
            cp16(sbm[nb] + soff + 16, wn_ + 1);
            CPCOMMIT();
            CPWAIT1();
        } else {
            CPWAIT0();
        }
        __syncthreads();

        #pragma unroll
        for (int ks = 0; ks < 2; ks++) {
            uint32_t af[4][4], bf[2][4];
            #pragma unroll
            for (int mt = 0; mt < 4; mt++) LDSM4(af[mt], aaddr[buf][mt] + ks * 32);
            #pragma unroll
            for (int bt = 0; bt < 2; bt++) LDSM4(bf[bt], baddr[buf][bt] + ks * 32);
            #pragma unroll
            for (int mt = 0; mt < 4; mt++)
                #pragma unroll
                for (int nt = 0; nt < 4; nt++)
                    MMA8(c[mt][nt], af[mt], bf[nt >> 1][(nt & 1) * 2], bf[nt >> 1][(nt & 1) * 2 + 1]);
        }
        __syncthreads();
    }

    float ws = *wsp;
    int g = lid >> 2, t4 = lid & 3;
    #pragma unroll
    for (int mt = 0; mt < 4; mt++) {
        int row = m0 + wm + mt * 16 + g;
        float rs0 = __fmul_rn(rowscale[row], ws);
        float rs1 = __fmul_rn(rowscale[row + 8], ws);
        float* cp0 = Cm + (size_t)row * Dn + n0 + wn;
        float* cp1 = cp0 + (size_t)8 * Dn;
        #pragma unroll
        for (int nt = 0; nt < 4; nt++) {
            int col = nt * 8 + t4 * 2;
            float2 v0, v1;
            v0.x = __fmul_rn((float)c[mt][nt][0], rs0);
            v0.y = __fmul_rn((float)c[mt][nt][1], rs0);
            v1.x = __fmul_rn((float)c[mt][nt][2], rs1);
            v1.y = __fmul_rn((float)c[mt][nt][3], rs1);
            *(float2*)(cp0 + col) = v0;
            *(float2*)(cp1 + col) = v1;
        }
    }
}

// ---------------- WKV: local + intra (unchanged from passing R14) ----------------
__global__ void __launch_bounds__(128, 2) k_wkv_kv() {
    int lane = threadIdx.x & 31, w = threadIdx.x >> 5;
    int idx = blockIdx.x * 4 + w;
    int c = idx & 31, h = (idx >> 5) & 15, b = idx >> 9;
    __shared__ ulonglong2 kw[4][64];
    __shared__ u64 rs[4][64];

    size_t rb = (size_t)(b * Tn + c * 64) * Dn + h * 64;
    const float2* kf = (const float2*)(g_rkvg[1] + rb);
    const float2* rf = (const float2*)(g_rkvg[0] + rb);
    const u64*    vu = (const u64*)(g_rkvg[2] + rb);
    u64*          yu = (u64*)(g_y + rb);

    u64 ls[64];
    #pragma unroll
    for (int s = 0; s < 64; s++) ls[s] = 0ull;
    #pragma unroll 1
    for (int t = 0; t < 64; t++) {
        float2 kk = kf[t * 512 + lane];
        float2 dd = ((const float2*)(g_wpow + (63 - t) * 1024 + h * 64))[lane];
        kw[w][2 * lane]     = make_ulonglong2(pk(kk.x, kk.x), pk(dd.x, dd.x));
        kw[w][2 * lane + 1] = make_ulonglong2(pk(kk.y, kk.y), pk(dd.y, dd.y));
        __syncwarp();
        u64 v2 = vu[t * 512 + lane];
        #pragma unroll
        for (int s = 0; s < 64; s++) {
            ulonglong2 q = kw[w][s];
            u64 tmp; F2MUL(tmp, q.x, v2);
            F2FMA(ls[s], q.y, tmp, ls[s]);   // ls += dd * (k*v)
        }
        __syncwarp();
    }
    u64* lp = (u64*)(g_local + (size_t)idx * 4096);
    #pragma unroll
    for (int s = 0; s < 64; s++) lp[s * 32 + lane] = ls[s];

    float2 wwv = ((const float2*)(g_wpow + 1024 + h * 64))[lane];
    float2 uev = ((const float2*)(g_ue + h * 64))[lane];
    kw[w][2 * lane].y     = pk(wwv.x, wwv.x);
    kw[w][2 * lane + 1].y = pk(wwv.y, wwv.y);
    u64 Q[64];
    #pragma unroll
    for (int s = 0; s < 64; s++) Q[s] = 0ull;
    #pragma unroll 1
    for (int t = 63; t >= 0; t--) {
        float2 kk = kf[t * 512 + lane];
        float2 rr = rf[t * 512 + lane];
        kw[w][2 * lane].x     = pk(kk.x, kk.x);
        kw[w][2 * lane + 1].x = pk(kk.y, kk.y);
        rs[w][2 * lane]       = pk(rr.x, rr.x);
        rs[w][2 * lane + 1]   = pk(rr.y, rr.y);
        float p = __fadd_rn(__fmul_rn(__fmul_rn(rr.x, uev.x), kk.x),
                            __fmul_rn(__fmul_rn(rr.y, uev.y), kk.y));
        #pragma unroll
        for (int o = 16; o; o >>= 1) p += __shfl_xor_sync(0xffffffffu, p, o);
        __syncwarp();
        u64 v2 = vu[t * 512 + lane];
        u64 y2; F2MUL(y2, pk(p, p), v2);
        #pragma unroll
        for (int s = 0; s < 64; s++) {
            ulonglong2 q = kw[w][s];
            u64 tmp; F2MUL(tmp, q.x, v2);
            F2FMA(Q[s], q.y, Q[s], tmp);
            F2FMA(y2, rs[w][s], Q[s], y2);
        }
        yu[t * 512 + lane] = y2;
        __syncwarp();
    }
}

// ---------------- WKV scan over chunks ----------------
__global__ void k_wkv_scan() {
    int bh = blockIdx.x;
    int h  = bh & 15;
    int tid = threadIdx.x;
    float cur[16], wc[16];
    #pragma unroll
    for (int j = 0; j < 16; j++) {
        cur[j] = 0.f;
        int e = tid + j * 256;
        wc[j] = g_wpow[64 * 1024 + h * 64 + (e >> 6)];
    }
    for (int c = 0; c < NC; c++) {
        size_t base = ((size_t)bh * NC + c) * 4096;
        #pragma unroll
        for (int j = 0; j < 16; j++) {
            int e = tid + j * 256;
            g_init[base + e] = cur[j];
            cur[j] = __fadd_rn(__fmul_rn(wc[j], cur[j]), g_local[base + e]);
        }
    }
}

// ---------------- WKV state term ----------------
__global__ void __launch_bounds__(128, 2) k_wkv_state() {
    int lane = threadIdx.x & 31, w = threadIdx.x >> 5;
    int idx = blockIdx.x * 4 + w;
    int c = idx & 31, h = (idx >> 5) & 15, b = idx >> 9;
    __shared__ u64 rp[4][64];

    size_t rb = (size_t)(b * Tn + c * 64) * Dn + h * 64;
    const float2* rf = (const float2*)(g_rkvg[0] + rb);
    u64* yu = (u64*)(g_y + rb);
    const u64* s0 = (const u64*)(g_init + (size_t)idx * 4096);

    u64 S[64];
    #pragma unroll
    for (int s = 0; s < 64; s++) S[s] = s0[s * 32 + lane];

    #pragma unroll 1
    for (int t = 0; t < 64; t++) {
        float2 rr = rf[t * 512 + lane];
        float2 cw = ((const float2*)(g_wpow + (t + 1) * 1024 + h * 64))[lane];
        float rx = __fmul_rn(rr.x, cw.x);
        float ry = __fmul_rn(rr.y, cw.y);
        rp[w][2 * lane]     = pk(rx, rx);
        rp[w][2 * lane + 1] = pk(ry, ry);
        __syncwarp();
        u64 y2 = yu[t * 512 + lane];
        #pragma unroll
        for (int s = 0; s < 64; s++)
            F2FMA(y2, rp[w][s], S[s], y2);
        yu[t * 512 + lane] = y2;
        __syncwarp();
    }
}

// ---------------- GroupNorm + SiLU + LN(4) + quant: 64 threads (2 warps) per row ----------------
__global__ void __launch_bounds__(64)
k_gn(const float* __restrict__ gn_g, const float* __restrict__ gn_b,
     const float* __restrict__ ln_g, const float* __restrict__ ln_b) {
    int row  = blockIdx.x;
    int tid  = threadIdx.x;            // owns d = tid*16 .. +15; head = tid>>2
    int lane = tid & 31, w = tid >> 5;
    __shared__ double sh[6];

    float yv[16];
    const float4* yr = (const float4*)(g_y + (size_t)row * Dn) + tid * 4;
    #pragma unroll
    for (int j = 0; j < 4; j++) {
        float4 a = yr[j];
        yv[4*j+0] = a.x; yv[4*j+1] = a.y; yv[4*j+2] = a.z; yv[4*j+3] = a.w;
    }

    // GroupNorm over 64 channels = 4 adjacent lanes (same warp)
    double gs;
    TREE16(gs, yv[i]);
    gs += __shfl_xor_sync(0xffffffffu, gs, 1);
    gs += __shfl_xor_sync(0xffffffffu, gs, 2);
    float mean = (float)(gs * (1.0 / 64.0));
    double s2;
    TREE16(s2, __fmul_rn(__fsub_rn(yv[i], mean), __fsub_rn(yv[i], mean)));
    s2 += __shfl_xor_sync(0xffffffffu, s2, 1);
    s2 += __shfl_xor_sync(0xffffffffu, s2, 2);
    float var  = (float)(s2 * (1.0 / 64.0));
    float rstd = (float)(1.0 / sqrt((double)__fadd_rn(var, 1e-5f)));

    const float4* ggp = (const float4*)gn_g + tid * 4;
    const float4* gbp = (const float4*)gn_b + tid * 4;
    const float4* gvp = (const float4*)(g_rkvg[3] + (size_t)row * Dn) + tid * 4;
    #pragma unroll
    for (int j = 0; j < 4; j++) {
        float4 gg = ggp[j], bb = gbp[j], gv4 = gvp[j];
        float ga[4] = {gg.x, gg.y, gg.z, gg.w};
        float ba[4] = {bb.x, bb.y, bb.z, bb.w};
        float gv[4] = {gv4.x, gv4.y, gv4.z, gv4.w};
        #pragma unroll
        for (int q = 0; q < 4; q++) {
            int i = 4*j + q;
            float yn = __fmul_rn(__fsub_rn(yv[i], mean), rstd);
            float yg = __fadd_rn(__fmul_rn(yn, ga[q]), ba[q]);
            float sig = __fdiv_rn(1.f, __fadd_rn(1.f, expf(-gv[q])));
            float sil = __fmul_rn(gv[q], sig);
            yv[i] = __fmul_rn(yg, sil);      // gated value
        }
    }

    // LayerNorm over full row (2-warp reduce)
    double ssum;
    TREE16(ssum, yv[i]);
    float m2 = (float)(red64(ssum, sh + 0, lane, w) * (1.0 / Dn));
    #pragma unroll
    for (int i = 0; i < 16; i++) yv[i] = __fsub_rn(yv[i], m2);
    double sv;
    TREE16(sv, __fmul_rn(yv[i], yv[i]));
    float var2 = (float)(red64(sv, sh + 2, lane, w) * (1.0 / Dn));
    float rst2 = (float)(1.0 / sqrt((double)__fadd_rn(var2, 1e-5f)));

    const float4* lgp = (const float4*)(ln_g + 4 * Dn) + tid * 4;
    const float4* lbp = (const float4*)(ln_b + 4 * Dn) + tid * 4;
    #pragma unroll
    for (int j = 0; j < 4; j++) {
        float4 gg = lgp[j], bb = lbp[j];
        float ga[4] = {gg.x, gg.y, gg.z, gg.w};
        float ba[4] = {bb.x, bb.y, bb.z, bb.w};
        #pragma unroll
        for (int q = 0; q < 4; q++) {
            int i = 4*j + q;
            float t1 = __fmul_rn(yv[i], rst2);
            yv[i] = __fadd_rn(__fmul_rn(t1, ga[q]), ba[q]);
        }
    }
    double sa;
    TREE16(sa, fabsf(yv[i]));
    float meanabs = (float)(red64(sa, sh + 4, lane, w) * (1.0 / Dn));
    float clipv = __fmul_rn(fmaxf(meanabs, 1e-8f), 2.5f);
    float scale = __fdiv_rn(clipv, 127.f);
    if (tid == 0) g_zscale[row] = scale;
    store_q16((signed char*)g_zq8 + (size_t)row * Dn + tid * 16, yv, scale);
}

// ---------------- launch ----------------
extern "C" void kernel_launch(void* const* d_in, const int* in_sizes, int n_in,
                              void* d_out, int out_size) {
    const float* x         = (const float*)d_in[0];
    const float* mu_r      = (const float*)d_in[1];
    const float* mu_k      = (const float*)d_in[2];
    const float* mu_v      = (const float*)d_in[3];
    const float* mu_g      = (const float*)d_in[4];
    const float* log_decay = (const float*)d_in[5];
    const float* u         = (const float*)d_in[6];
    const float* proj_w    = (const float*)d_in[7];
    const float* ln_g      = (const float*)d_in[8];
    const float* ln_b      = (const float*)d_in[9];
    const float* gn_g      = (const float*)d_in[10];
    const float* gn_b      = (const float*)d_in[11];

    int4 *xq8, *wq8, *zq8;
    float *rkvg, *xscale, *zscale, *wscale;
    cudaGetSymbolAddress((void**)&xq8,    g_xq8);
    cudaGetSymbolAddress((void**)&wq8,    g_wq8);
    cudaGetSymbolAddress((void**)&zq8,    g_zq8);
    cudaGetSymbolAddress((void**)&rkvg,   g_rkvg);
    cudaGetSymbolAddress((void**)&xscale, g_xscale);
    cudaGetSymbolAddress((void**)&zscale, g_zscale);
    cudaGetSymbolAddress((void**)&wscale, g_wscale);

    k_params<<<1, 1024>>>(log_decay, u);
    k_wscale<<<5, 256>>>(proj_w);
    k_wquant<<<5 * Dn * Dn / 256, 256>>>(proj_w);
    k_prep<<<BT, 64>>>(x, mu_r, mu_k, mu_v, mu_g, ln_g, ln_b);

    dim3 ggrid(Dn / 128, BT / 128);
    for (int v = 0; v < 4; v++)
        k_gemm_i8<<<ggrid, 256>>>(xq8 + (size_t)v * (BT * Dn / 16),
                                  wq8 + (size_t)v * (Dn * Dn / 16),
                                  xscale + (size_t)v * BT,
                                  wscale + v,
                                  rkvg + (size_t)v * BT * Dn);

    k_wkv_kv<<<Bn * Hn * NC / 4, 128>>>();
    k_wkv_scan<<<Bn * Hn, 256>>>();
    k_wkv_state<<<Bn * Hn * NC / 4, 128>>>();

    k_gn<<<BT, 64>>>(gn_g, gn_b, ln_g, ln_b);

    k_gemm_i8<<<ggrid, 256>>>(zq8, wq8 + (size_t)4 * (Dn * Dn / 16),
                              zscale, wscale + 4, (float*)d_out);
}

// round 16
// speedup vs baseline: 1.0014x; 1.0014x over previous
#include <cuda_runtime.h>
#include <math.h>
#include <stdint.h>

// Problem constants
#define Bn 4
#define Tn 2048
#define Dn 1024
#define Hn 16
#define Sn 64
#define NC 32
#define BT (Bn*Tn)   // 8192 rows

typedef unsigned long long u64;

// ---------------- scratch ----------------
__device__ int4  g_xq8[4][BT*Dn/16];
__device__ float g_xscale[4][BT];
__device__ int4  g_wq8[5][Dn*Dn/16];
__device__ float g_wscale[5];
__device__ int4  g_zq8[BT*Dn/16];
__device__ float g_zscale[BT];
__device__ float g_rkvg[4][BT*Dn];
__device__ float g_y[BT*Dn];
__device__ float g_local[Bn*Hn*NC*Sn*Sn];
__device__ float g_init [Bn*Hn*NC*Sn*Sn];
__device__ float g_wpow[65*1024];
__device__ float g_ue[Hn*Sn];

// ---------------- f32x2 packed helpers ----------------
#define F2MUL(d, a, b)    asm("mul.rn.f32x2 %0, %1, %2;" : "=l"(d) : "l"(a), "l"(b))
#define F2FMA(d, a, b, c) asm("fma.rn.f32x2 %0, %1, %2, %3;" : "=l"(d) : "l"(a), "l"(b), "l"(c))
__device__ __forceinline__ u64 pk(float x, float y) {
    u64 r; asm("mov.b64 %0, {%1, %2};" : "=l"(r) : "f"(x), "f"(y)); return r;
}

// ---------------- reductions ----------------
__device__ __forceinline__ double wrD(double v) {
    #pragma unroll
    for (int o = 16; o; o >>= 1) v += __shfl_xor_sync(0xffffffffu, v, o);
    return v;
}

// ILP fp64 tree over 32 floats (4 independent chains)
#define TREE32(res, expr_i) do { \
    double a0 = 0.0, a1 = 0.0, a2 = 0.0, a3 = 0.0; \
    _Pragma("unroll") \
    for (int _j = 0; _j < 8; _j++) { \
        { int i = 4*_j + 0; a0 += (double)(expr_i); } \
        { int i = 4*_j + 1; a1 += (double)(expr_i); } \
        { int i = 4*_j + 2; a2 += (double)(expr_i); } \
        { int i = 4*_j + 3; a3 += (double)(expr_i); } \
    } \
    res = (a0 + a1) + (a2 + a3); \
} while (0)

// block reduce for k_wscale only (256 threads)
__device__ __forceinline__ double brD(double v, double* red) {
    int tid = threadIdx.x, lane = tid & 31, wid = tid >> 5;
    int nw = blockDim.x >> 5;
    v = wrD(v);
    if (lane == 0) red[wid] = v;
    __syncthreads();
    if (tid == 0) {
        double r = red[0];
        for (int i = 1; i < nw; i++) r += red[i];
        red[0] = r;
    }
    __syncthreads();
    double r = red[0];
    __syncthreads();
    return r;
}

// ---------------- misc GEMM helpers ----------------
__device__ __forceinline__ uint32_t smem_u32(const void* p) {
    uint32_t a;
    asm("{ .reg .u64 t; cvta.to.shared.u64 t, %1; cvt.u32.u64 %0, t; }" : "=r"(a) : "l"(p));
    return a;
}
__device__ __forceinline__ void cp16(uint32_t dst, const void* src) {
    asm volatile("cp.async.cg.shared.global [%0], [%1], 16;" :: "r"(dst), "l"(src) : "memory");
}
#define CPCOMMIT()  asm volatile("cp.async.commit_group;" ::: "memory")
#define CPWAIT1()   asm volatile("cp.async.wait_group 1;" ::: "memory")
#define CPWAIT0()   asm volatile("cp.async.wait_group 0;" ::: "memory")
#define LDSM4(r, addr) \
    asm volatile("ldmatrix.sync.aligned.m8n8.x4.shared.b16 {%0,%1,%2,%3}, [%4];" \
        : "=r"((r)[0]), "=r"((r)[1]), "=r"((r)[2]), "=r"((r)[3]) : "r"(addr))
#define MMA8(c, a, b0, b1) \
    asm volatile("mma.sync.aligned.m16n8k32.row.col.s32.s8.s8.s32 " \
        "{%0,%1,%2,%3}, {%4,%5,%6,%7}, {%8,%9}, {%0,%1,%2,%3};" \
        : "+r"((c)[0]), "+r"((c)[1]), "+r"((c)[2]), "+r"((c)[3]) \
        : "r"((a)[0]), "r"((a)[1]), "r"((a)[2]), "r"((a)[3]), "r"(b0), "r"(b1))

// ---------------- precompute ----------------
__global__ void k_params(const float* __restrict__ log_decay, const float* __restrict__ u) {
    int i = threadIdx.x;
    float eld = expf(log_decay[i]);
    float wf  = expf(-eld);
    float lw  = logf(fmaxf(wf, 1e-38f));
    for (int n = 0; n <= 64; n++)
        g_wpow[n * 1024 + i] = expf(__fmul_rn((float)n, lw));
    g_ue[i] = expf(u[i]);
}

// ---------------- weight quantization ----------------
__global__ void k_wscale(const float* __restrict__ w) {
    __shared__ double red[8];
    const float* p = w + (size_t)blockIdx.x * Dn * Dn;
    double s = 0.0;
    for (int i = threadIdx.x; i < Dn * Dn; i += 256) s += (double)fabsf(p[i]);
    double tot = brD(s, red);
    if (threadIdx.x == 0)
        g_wscale[blockIdx.x] = fmaxf((float)(tot / (double)(Dn * Dn)), 1e-8f);
}

__global__ void k_wquant(const float* __restrict__ w) {
    int i = blockIdx.x * 256 + threadIdx.x;
    int m = i / (Dn * Dn);
    float s  = g_wscale[m];
    float vn = __fdiv_rn(w[i], s);
    vn = fminf(fmaxf(vn, -1.f), 1.f);
    ((signed char*)g_wq8)[i] = (signed char)(int)rintf(vn);
}

// ---------------- int8 pack+store: 32 consecutive bytes per lane ----------------
__device__ __forceinline__ void store_q32(signed char* base, const float* yv, float scale) {
    int w[8];
    #pragma unroll
    for (int j = 0; j < 8; j++) {
        int q0 = (int)rintf(fminf(fmaxf(__fdiv_rn(yv[4*j+0], scale), -127.f), 127.f));
        int q1 = (int)rintf(fminf(fmaxf(__fdiv_rn(yv[4*j+1], scale), -127.f), 127.f));
        int q2 = (int)rintf(fminf(fmaxf(__fdiv_rn(yv[4*j+2], scale), -127.f), 127.f));
        int q3 = (int)rintf(fminf(fmaxf(__fdiv_rn(yv[4*j+3], scale), -127.f), 127.f));
        w[j] = (q0 & 0xff) | ((q1 & 0xff) << 8) | ((q2 & 0xff) << 16) | ((q3 & 0xff) << 24);
    }
    ((int4*)base)[0] = make_int4(w[0], w[1], w[2], w[3]);
    ((int4*)base)[1] = make_int4(w[4], w[5], w[6], w[7]);
}

// ---------------- token shift + LN + act quant: ONE WARP PER (row, variant) ----------------
// grid 4096 x 256thr = 32768 warps; warp handles row = gw>>2, variant = gw&3.
// Only inp[32] kept live (computed on the fly) -> no spills.
__global__ void __launch_bounds__(256)
k_prep(const float* __restrict__ x,
       const float* __restrict__ mu_r, const float* __restrict__ mu_k,
       const float* __restrict__ mu_v, const float* __restrict__ mu_g,
       const float* __restrict__ ln_g, const float* __restrict__ ln_b) {
    int gw   = blockIdx.x * 8 + (threadIdx.x >> 5);   // global warp id
    int lane = threadIdx.x & 31;
    int row  = gw >> 2;
    int v    = gw & 3;
    int t    = row % Tn;

    const float* mu = (v == 0) ? mu_r : (v == 1) ? mu_k : (v == 2) ? mu_v : mu_g;
    const float4* xr  = (const float4*)(x + (size_t)row * Dn) + lane * 8;
    const float4* xp  = (const float4*)(x + (size_t)(row - 1) * Dn) + lane * 8;
    const float4* muv = (const float4*)mu + lane * 8;

    float inp[32];
    #pragma unroll
    for (int j = 0; j < 8; j++) {
        float4 a = xr[j];
        float4 p = (t > 0) ? xp[j] : make_float4(0.f, 0.f, 0.f, 0.f);
        float4 m = muv[j];
        inp[4*j+0] = __fadd_rn(a.x, __fmul_rn(__fsub_rn(p.x, a.x), m.x));
        inp[4*j+1] = __fadd_rn(a.y, __fmul_rn(__fsub_rn(p.y, a.y), m.y));
        inp[4*j+2] = __fadd_rn(a.z, __fmul_rn(__fsub_rn(p.z, a.z), m.z));
        inp[4*j+3] = __fadd_rn(a.w, __fmul_rn(__fsub_rn(p.w, a.w), m.w));
    }

    double s;
    TREE32(s, inp[i]);
    float mean = (float)(wrD(s) * (1.0 / Dn));

    #pragma unroll
    for (int i = 0; i < 32; i++) inp[i] = __fsub_rn(inp[i], mean);   // dev
    double s2;
    TREE32(s2, __fmul_rn(inp[i], inp[i]));
    float var  = (float)(wrD(s2) * (1.0 / Dn));
    float rstd = (float)(1.0 / sqrt((double)__fadd_rn(var, 1e-5f)));

    const float4* gp = (const float4*)(ln_g + v * Dn) + lane * 8;
    const float4* bp = (const float4*)(ln_b + v * Dn) + lane * 8;
    #pragma unroll
    for (int j = 0; j < 8; j++) {
        float4 gg = gp[j], bb = bp[j];
        float ga[4] = {gg.x, gg.y, gg.z, gg.w};
        float ba[4] = {bb.x, bb.y, bb.z, bb.w};
        #pragma unroll
        for (int q = 0; q < 4; q++) {
            int i = 4*j + q;
            float t1 = __fmul_rn(inp[i], rstd);
            inp[i] = __fadd_rn(__fmul_rn(t1, ga[q]), ba[q]);            // yv
        }
    }
    double sa;
    TREE32(sa, fabsf(inp[i]));
    float meanabs = (float)(wrD(sa) * (1.0 / Dn));
    float clipv = __fmul_rn(fmaxf(meanabs, 1e-8f), 2.5f);
    float scale = __fdiv_rn(clipv, 127.f);
    if (lane == 0) g_xscale[v][row] = scale;
    store_q32((signed char*)g_xq8[v] + (size_t)row * Dn + lane * 32, inp, scale);
}

// ---------------- int8 tensor-core GEMM via mma.sync (exact int32 accum) ----------------
#define ROWB 80
__global__ void __launch_bounds__(256, 2)
k_gemm_i8(const int4* __restrict__ A, const int4* __restrict__ W,
          const float* __restrict__ rowscale, const float* __restrict__ wsp,
          float* __restrict__ Cm) {
    __shared__ __align__(16) signed char As[2][128 * ROWB];
    __shared__ __align__(16) signed char Bs[2][128 * ROWB];
    int tid = threadIdx.x, lid = tid & 31, wid = tid >> 5;
    int m0 = blockIdx.y * 128, n0 = blockIdx.x * 128;
    int wm = (wid & 1) * 64, wn = (wid >> 1) * 32;

    int lrow = tid >> 1;
    int lc   = (tid & 1) * 2;
    const int4* Ag = A + (size_t)(m0 + lrow) * 64 + lc;
    const int4* Wg = W + (size_t)(n0 + lrow) * 64 + lc;
    uint32_t soff = (uint32_t)(lrow * ROWB + lc * 16);
    uint32_t sa[2] = {smem_u32(As[0]), smem_u32(As[1])};
    uint32_t sbm[2] = {smem_u32(Bs[0]), smem_u32(Bs[1])};

    int arow   = (lid & 7) + ((lid >> 3) & 1) * 8;
    int akhalf = lid >> 4;
    int brow   = (lid & 7) + (lid >> 4) * 8;
    int bkhalf = (lid >> 3) & 1;
    uint32_t aaddr[2][4], baddr[2][2];
    #pragma unroll
    for (int buf = 0; buf < 2; buf++) {
        #pragma unroll
        for (int mt = 0; mt < 4; mt++)
            aaddr[buf][mt] = sa[buf] + (uint32_t)((wm + mt * 16 + arow) * ROWB + akhalf * 16);
        #pragma unroll
        for (int bt = 0; bt < 2; bt++)
            baddr[buf][bt] = sbm[buf] + (uint32_t)((wn + bt * 16 + brow) * ROWB + bkhalf * 16);
    }

    int c[4][4][4];
    #pragma unroll
    for (int mt = 0; mt < 4; mt++)
        #pragma unroll
        for (int nt = 0; nt < 4; nt++)
            #pragma unroll
            for (int q = 0; q < 4; q++) c[mt][nt][q] = 0;

    cp16(sa[0] + soff,       Ag);
    cp16(sa[0] + soff + 16,  Ag + 1);
    cp16(sbm[0] + soff,      Wg);
    cp16(sbm[0] + soff + 16, Wg + 1);
    CPCOMMIT();

    for (int kb = 0; kb < 16; kb++) {
        int buf = kb & 1;
        if (kb < 15) {
            const int4* an = Ag + (kb + 1) * 4;
            const int4* wn_ = Wg + (kb + 1) * 4;
            int nb = buf ^ 1;
            cp16(sa[nb] + soff,       an);
            cp16(sa[nb] + soff + 16,  an + 1);
            cp16(sbm[nb] + soff,      wn_);
            cp16(sbm[nb] + soff + 16, wn_ + 1);
            CPCOMMIT();
            CPWAIT1();
        } else {
            CPWAIT0();
        }
        __syncthreads();

        #pragma unroll
        for (int ks = 0; ks < 2; ks++) {
            uint32_t af[4][4], bf[2][4];
            #pragma unroll
            for (int mt = 0; mt < 4; mt++) LDSM4(af[mt], aaddr[buf][mt] + ks * 32);
            #pragma unroll
            for (int bt = 0; bt < 2; bt++) LDSM4(bf[bt], baddr[buf][bt] + ks * 32);
            #pragma unroll
            for (int mt = 0; mt < 4; mt++)
                #pragma unroll
                for (int nt = 0; nt < 4; nt++)
                    MMA8(c[mt][nt], af[mt], bf[nt >> 1][(nt & 1) * 2], bf[nt >> 1][(nt & 1) * 2 + 1]);
        }
        __syncthreads();
    }

    float ws = *wsp;
    int g = lid >> 2, t4 = lid & 3;
    #pragma unroll
    for (int mt = 0; mt < 4; mt++) {
        int row = m0 + wm + mt * 16 + g;
        float rs0 = __fmul_rn(rowscale[row], ws);
        float rs1 = __fmul_rn(rowscale[row + 8], ws);
        float* cp0 = Cm + (size_t)row * Dn + n0 + wn;
        float* cp1 = cp0 + (size_t)8 * Dn;
        #pragma unroll
        for (int nt = 0; nt < 4; nt++) {
            int col = nt * 8 + t4 * 2;
            float2 v0, v1;
            v0.x = __fmul_rn((float)c[mt][nt][0], rs0);
            v0.y = __fmul_rn((float)c[mt][nt][1], rs0);
            v1.x = __fmul_rn((float)c[mt][nt][2], rs1);
            v1.y = __fmul_rn((float)c[mt][nt][3], rs1);
            *(float2*)(cp0 + col) = v0;
            *(float2*)(cp1 + col) = v1;
        }
    }
}

// ---------------- WKV: local + intra ----------------
__global__ void __launch_bounds__(128, 2) k_wkv_kv() {
    int lane = threadIdx.x & 31, w = threadIdx.x >> 5;
    int idx = blockIdx.x * 4 + w;
    int c = idx & 31, h = (idx >> 5) & 15, b = idx >> 9;
    __shared__ ulonglong2 kw[4][64];
    __shared__ u64 rs[4][64];

    size_t rb = (size_t)(b * Tn + c * 64) * Dn + h * 64;
    const float2* kf = (const float2*)(g_rkvg[1] + rb);
    const float2* rf = (const float2*)(g_rkvg[0] + rb);
    const u64*    vu = (const u64*)(g_rkvg[2] + rb);
    u64*          yu = (u64*)(g_y + rb);

    u64 ls[64];
    #pragma unroll
    for (int s = 0; s < 64; s++) ls[s] = 0ull;
    #pragma unroll 1
    for (int t = 0; t < 64; t++) {
        float2 kk = kf[t * 512 + lane];
        float2 dd = ((const float2*)(g_wpow + (63 - t) * 1024 + h * 64))[lane];
        kw[w][2 * lane]     = make_ulonglong2(pk(kk.x, kk.x), pk(dd.x, dd.x));
        kw[w][2 * lane + 1] = make_ulonglong2(pk(kk.y, kk.y), pk(dd.y, dd.y));
        __syncwarp();
        u64 v2 = vu[t * 512 + lane];
        #pragma unroll
        for (int s = 0; s < 64; s++) {
            ulonglong2 q = kw[w][s];
            u64 tmp; F2MUL(tmp, q.x, v2);
            F2FMA(ls[s], q.y, tmp, ls[s]);   // ls += dd * (k*v)
        }
        __syncwarp();
    }
    u64* lp = (u64*)(g_local + (size_t)idx * 4096);
    #pragma unroll
    for (int s = 0; s < 64; s++) lp[s * 32 + lane] = ls[s];

    float2 wwv = ((const float2*)(g_wpow + 1024 + h * 64))[lane];
    float2 uev = ((const float2*)(g_ue + h * 64))[lane];
    kw[w][2 * lane].y     = pk(wwv.x, wwv.x);
    kw[w][2 * lane + 1].y = pk(wwv.y, wwv.y);
    u64 Q[64];
    #pragma unroll
    for (int s = 0; s < 64; s++) Q[s] = 0ull;
    #pragma unroll 1
    for (int t = 63; t >= 0; t--) {
        float2 kk = kf[t * 512 + lane];
        float2 rr = rf[t * 512 + lane];
        kw[w][2 * lane].x     = pk(kk.x, kk.x);
        kw[w][2 * lane + 1].x = pk(kk.y, kk.y);
        rs[w][2 * lane]       = pk(rr.x, rr.x);
        rs[w][2 * lane + 1]   = pk(rr.y, rr.y);
        float p = __fadd_rn(__fmul_rn(__fmul_rn(rr.x, uev.x), kk.x),
                            __fmul_rn(__fmul_rn(rr.y, uev.y), kk.y));
        #pragma unroll
        for (int o = 16; o; o >>= 1) p += __shfl_xor_sync(0xffffffffu, p, o);
        __syncwarp();
        u64 v2 = vu[t * 512 + lane];
        u64 y2; F2MUL(y2, pk(p, p), v2);
        #pragma unroll
        for (int s = 0; s < 64; s++) {
            ulonglong2 q = kw[w][s];
            u64 tmp; F2MUL(tmp, q.x, v2);
            F2FMA(Q[s], q.y, Q[s], tmp);
            F2FMA(y2, rs[w][s], Q[s], y2);
        }
        yu[t * 512 + lane] = y2;
        __syncwarp();
    }
}

// ---------------- WKV scan over chunks ----------------
__global__ void k_wkv_scan() {
    int bh = blockIdx.x;
    int h  = bh & 15;
    int tid = threadIdx.x;
    float cur[16], wc[16];
    #pragma unroll
    for (int j = 0; j < 16; j++) {
        cur[j] = 0.f;
        int e = tid + j * 256;
        wc[j] = g_wpow[64 * 1024 + h * 64 + (e >> 6)];
    }
    for (int c = 0; c < NC; c++) {
        size_t base = ((size_t)bh * NC + c) * 4096;
        #pragma unroll
        for (int j = 0; j < 16; j++) {
            int e = tid + j * 256;
            g_init[base + e] = cur[j];
            cur[j] = __fadd_rn(__fmul_rn(wc[j], cur[j]), g_local[base + e]);
        }
    }
}

// ---------------- WKV state term ----------------
__global__ void __launch_bounds__(128, 2) k_wkv_state() {
    int lane = threadIdx.x & 31, w = threadIdx.x >> 5;
    int idx = blockIdx.x * 4 + w;
    int c = idx & 31, h = (idx >> 5) & 15, b = idx >> 9;
    __shared__ u64 rp[4][64];

    size_t rb = (size_t)(b * Tn + c * 64) * Dn + h * 64;
    const float2* rf = (const float2*)(g_rkvg[0] + rb);
    u64* yu = (u64*)(g_y + rb);
    const u64* s0 = (const u64*)(g_init + (size_t)idx * 4096);

    u64 S[64];
    #pragma unroll
    for (int s = 0; s < 64; s++) S[s] = s0[s * 32 + lane];

    #pragma unroll 1
    for (int t = 0; t < 64; t++) {
        float2 rr = rf[t * 512 + lane];
        float2 cw = ((const float2*)(g_wpow + (t + 1) * 1024 + h * 64))[lane];
        float rx = __fmul_rn(rr.x, cw.x);
        float ry = __fmul_rn(rr.y, cw.y);
        rp[w][2 * lane]     = pk(rx, rx);
        rp[w][2 * lane + 1] = pk(ry, ry);
        __syncwarp();
        u64 y2 = yu[t * 512 + lane];
        #pragma unroll
        for (int s = 0; s < 64; s++)
            F2FMA(y2, rp[w][s], S[s], y2);
        yu[t * 512 + lane] = y2;
        __syncwarp();
    }
}

// ---------------- GroupNorm + SiLU + LN(4) + quant: ONE WARP PER ROW (R14 form) ----------------
__global__ void __launch_bounds__(256)
k_gn(const float* __restrict__ gn_g, const float* __restrict__ gn_b,
     const float* __restrict__ ln_g, const float* __restrict__ ln_b) {
    int row  = blockIdx.x * 8 + (threadIdx.x >> 5);
    int lane = threadIdx.x & 31;

    float yv[32];
    const float4* yr = (const float4*)(g_y + (size_t)row * Dn) + lane * 8;
    #pragma unroll
    for (int j = 0; j < 8; j++) {
        float4 a = yr[j];
        yv[4*j+0] = a.x; yv[4*j+1] = a.y; yv[4*j+2] = a.z; yv[4*j+3] = a.w;
    }

    // GroupNorm over 64 channels = this lane + partner (lane^1)
    double gs;
    TREE32(gs, yv[i]);
    gs += __shfl_xor_sync(0xffffffffu, gs, 1);
    float mean = (float)(gs * (1.0 / 64.0));
    double s2 = 0.0;
    #pragma unroll
    for (int i = 0; i < 32; i++) {
        float d = __fsub_rn(yv[i], mean);
        yv[i] = d;
        s2 += (double)__fmul_rn(d, d);
    }
    s2 += __shfl_xor_sync(0xffffffffu, s2, 1);
    float var  = (float)(s2 * (1.0 / 64.0));
    float rstd = (float)(1.0 / sqrt((double)__fadd_rn(var, 1e-5f)));

    const float4* ggp = (const float4*)gn_g + lane * 8;
    const float4* gbp = (const float4*)gn_b + lane * 8;
    const float4* gvp = (const float4*)(g_rkvg[3] + (size_t)row * Dn) + lane * 8;
    double ssum = 0.0;
    #pragma unroll
    for (int j = 0; j < 8; j++) {
        float4 gg = ggp[j], bb = gbp[j], gv4 = gvp[j];
        float ga[4] = {gg.x, gg.y, gg.z, gg.w};
        float ba[4] = {bb.x, bb.y, bb.z, bb.w};
        float gv[4] = {gv4.x, gv4.y, gv4.z, gv4.w};
        #pragma unroll
        for (int q = 0; q < 4; q++) {
            int i = 4*j + q;
            float yn = __fmul_rn(yv[i], rstd);
            float yg = __fadd_rn(__fmul_rn(yn, ga[q]), ba[q]);
            float sig = __fdiv_rn(1.f, __fadd_rn(1.f, expf(-gv[q])));
            float sil = __fmul_rn(gv[q], sig);
            yv[i] = __fmul_rn(yg, sil);
            ssum += (double)yv[i];
        }
    }

    // LayerNorm over full row (warp-wide)
    float m2 = (float)(wrD(ssum) * (1.0 / Dn));
    double sv = 0.0;
    #pragma unroll
    for (int i = 0; i < 32; i++) {
        float d = __fsub_rn(yv[i], m2);
        yv[i] = d;
        sv += (double)__fmul_rn(d, d);
    }
    float var2 = (float)(wrD(sv) * (1.0 / Dn));
    float rst2 = (float)(1.0 / sqrt((double)__fadd_rn(var2, 1e-5f)));

    const float4* lgp = (const float4*)(ln_g + 4 * Dn) + lane * 8;
    const float4* lbp = (const float4*)(ln_b + 4 * Dn) + lane * 8;
    double sa = 0.0;
    #pragma unroll
    for (int j = 0; j < 8; j++) {
        float4 gg = lgp[j], bb = lbp[j];
        float ga[4] = {gg.x, gg.y, gg.z, gg.w};
        float ba[4] = {bb.x, bb.y, bb.z, bb.w};
        #pragma unroll
        for (int q = 0; q < 4; q++) {
            int i = 4*j + q;
            float t1 = __fmul_rn(yv[i], rst2);
            float y2 = __fadd_rn(__fmul_rn(t1, ga[q]), ba[q]);
            yv[i] = y2;
            sa += (double)fabsf(y2);
        }
    }
    float meanabs = (float)(wrD(sa) * (1.0 / Dn));
    float clipv = __fmul_rn(fmaxf(meanabs, 1e-8f), 2.5f);
    float scale = __fdiv_rn(clipv, 127.f);
    if (lane == 0) g_zscale[row] = scale;
    store_q32((signed char*)g_zq8 + (size_t)row * Dn + lane * 32, yv, scale);
}

// ---------------- launch ----------------
extern "C" void kernel_launch(void* const* d_in, const int* in_sizes, int n_in,
                              void* d_out, int out_size) {
    const float* x         = (const float*)d_in[0];
    const float* mu_r      = (const float*)d_in[1];
    const float* mu_k      = (const float*)d_in[2];
    const float* mu_v      = (const float*)d_in[3];
    const float* mu_g      = (const float*)d_in[4];
    const float* log_decay = (const float*)d_in[5];
    const float* u         = (const float*)d_in[6];
    const float* proj_w    = (const float*)d_in[7];
    const float* ln_g      = (const float*)d_in[8];
    const float* ln_b      = (const float*)d_in[9];
    const float* gn_g      = (const float*)d_in[10];
    const float* gn_b      = (const float*)d_in[11];

    int4 *xq8, *wq8, *zq8;
    float *rkvg, *xscale, *zscale, *wscale;
    cudaGetSymbolAddress((void**)&xq8,    g_xq8);
    cudaGetSymbolAddress((void**)&wq8,    g_wq8);
    cudaGetSymbolAddress((void**)&zq8,    g_zq8);
    cudaGetSymbolAddress((void**)&rkvg,   g_rkvg);
    cudaGetSymbolAddress((void**)&xscale, g_xscale);
    cudaGetSymbolAddress((void**)&zscale, g_zscale);
    cudaGetSymbolAddress((void**)&wscale, g_wscale);

    k_params<<<1, 1024>>>(log_decay, u);
    k_wscale<<<5, 256>>>(proj_w);
    k_wquant<<<5 * Dn * Dn / 256, 256>>>(proj_w);
    k_prep<<<BT * 4 / 8, 256>>>(x, mu_r, mu_k, mu_v, mu_g, ln_g, ln_b);

    dim3 ggrid(Dn / 128, BT / 128);
    for (int v = 0; v < 4; v++)
        k_gemm_i8<<<ggrid, 256>>>(xq8 + (size_t)v * (BT * Dn / 16),
                                  wq8 + (size_t)v * (Dn * Dn / 16),
                                  xscale + (size_t)v * BT,
                                  wscale + v,
                                  rkvg + (size_t)v * BT * Dn);

    k_wkv_kv<<<Bn * Hn * NC / 4, 128>>>();
    k_wkv_scan<<<Bn * Hn, 256>>>();
    k_wkv_state<<<Bn * Hn * NC / 4, 128>>>();

    k_gn<<<BT / 8, 256>>>(gn_g, gn_b, ln_g, ln_b);

    k_gemm_i8<<<ggrid, 256>>>(zq8, wq8 + (size_t)4 * (Dn * Dn / 16),
                              zscale, wscale + 4, (float*)d_out);
}